// round 17
// baseline (speedup 1.0000x reference)
#include <cuda_runtime.h>
#include <cuda_fp16.h>
#include <math.h>
#include <cstdint>

// Problem constants
#define N_ 128
#define K_ 64
#define C_ 64
#define ROWS_ (N_ * K_)   // 8192

// Scratch (device globals: no allocation allowed)
__device__ float g_U [ROWS_ * C_];   // um * ug
__device__ float g_A [ROWS_ * C_];   // h @ Wb1[:C]  + bb1
__device__ float g_B [ROWS_ * C_];   // h @ Wb1[C:]
__device__ float g_Ag[ROWS_ * C_];   // h @ Wbg1[:C] + bbg1
__device__ float g_Bg[ROWS_ * C_];   // h @ Wbg1[C:]
// Precomputed fp16 W image for MAIN kernel: [0,9216) Wb | [9216,18432) Wg
__device__ unsigned char g_Wimg[18432];

__device__ __forceinline__ float tanh_fast(float x) {
    float y;
    asm("tanh.approx.f32 %0, %1;" : "=f"(y) : "f"(x));
    return y;
}
__device__ __forceinline__ uint32_t tanh_f16x2(uint32_t x) {
    uint32_t y;
    asm("tanh.approx.f16x2 %0, %1;" : "=r"(y) : "r"(x));
    return y;
}
__device__ __forceinline__ float fast_sigmoid(float x) {
    return __fdividef(1.0f, 1.0f + __expf(-x));
}

// pack two fp32 into f16x2 (first arg -> low 16 bits)
__device__ __forceinline__ uint32_t pack_f16x2(float lo, float hi) {
    uint32_t r;
    asm("cvt.rn.f16x2.f32 %0, %1, %2;" : "=r"(r) : "f"(hi), "f"(lo));
    return r;
}
// pack with hi/lo residual split
__device__ __forceinline__ void dpack(float v0, float v1, uint32_t& h, uint32_t& l) {
    h = pack_f16x2(v0, v1);
    const float2 f = __half22float2(*(__half2*)&h);
    l = pack_f16x2(v0 - f.x, v1 - f.y);
}

__device__ __forceinline__ uint32_t smem_to_u32(const void* p) {
    uint32_t a;
    asm("{ .reg .u64 t; cvta.to.shared.u64 t, %1; cvt.u32.u64 %0, t; }"
        : "=r"(a) : "l"(p));
    return a;
}

// warp-level fp16 HMMA, m16n8k16, row.col, f32 accumulate (base-target PTX)
__device__ __forceinline__ void mma16816(float acc[4], const uint32_t a[4],
                                         uint32_t b0, uint32_t b1) {
    asm volatile(
        "mma.sync.aligned.m16n8k16.row.col.f32.f16.f16.f32 "
        "{%0,%1,%2,%3}, {%4,%5,%6,%7}, {%8,%9}, {%0,%1,%2,%3};"
        : "+f"(acc[0]), "+f"(acc[1]), "+f"(acc[2]), "+f"(acc[3])
        : "r"(a[0]), "r"(a[1]), "r"(a[2]), "r"(a[3]), "r"(b0), "r"(b1));
}

__device__ __forceinline__ void ldm_x4(uint32_t r[4], uint32_t addr) {
    asm volatile(
        "ldmatrix.sync.aligned.m8n8.x4.shared.b16 {%0,%1,%2,%3}, [%4];"
        : "=r"(r[0]), "=r"(r[1]), "=r"(r[2]), "=r"(r[3]) : "r"(addr));
}

// ---------------------------------------------------------------------------
// Kernel 1 (tensor-core prep; R16 + paired binary GEMMs for ILP):
// 128 blocks x 128 threads (4 warps x 16-row strips); full chain in registers.
// Block 128 builds the main kernel's fp16 W image.
// ---------------------------------------------------------------------------
#define PP 144          // W/x image pitch (bytes)
#define P_WLIN  0
#define P_WU1   18432
#define P_WU2   36864
#define P_WUG1  55296
#define P_WUG2  73728
#define P_WB1A  92160
#define P_WB1B  101376
#define P_WBG1A 110592
#define P_WBG1B 119808
#define P_XH    129024
#define P_XL    138240
#define PREP_SMEM_BYTES 147456

__global__ __launch_bounds__(128)
void prep_kernel(const float* __restrict__ x,
                 const float* __restrict__ Wlin, const float* __restrict__ blin,
                 const float* __restrict__ Wu1,  const float* __restrict__ bu1,
                 const float* __restrict__ Wu2,  const float* __restrict__ bu2,
                 const float* __restrict__ Wug1, const float* __restrict__ bug1,
                 const float* __restrict__ Wug2, const float* __restrict__ bug2,
                 const float* __restrict__ Wb1,  const float* __restrict__ bb1,
                 const float* __restrict__ Wbg1, const float* __restrict__ bbg1,
                 const float* __restrict__ Wb2,  const float* __restrict__ Wbg2)
{
    const int tid = threadIdx.x;

    // --- block 128: build fp16 W image for the MAIN kernel (vectorized) ---
    if (blockIdx.x == 128) {
        for (int tq = tid; tq < 1024; tq += 128) {
            const int c  = tq & 63;
            const int kb = (tq >> 6) * 4;
            const int off = c * PP + kb * 2;
            {
                const uint32_t h0 = pack_f16x2(Wb2[(kb + 0) * 64 + c], Wb2[(kb + 1) * 64 + c]);
                const uint32_t h1 = pack_f16x2(Wb2[(kb + 2) * 64 + c], Wb2[(kb + 3) * 64 + c]);
                *(uint2*)(g_Wimg + off) = make_uint2(h0, h1);
            }
            {
                const uint32_t h0 = pack_f16x2(Wbg2[(kb + 0) * 64 + c], Wbg2[(kb + 1) * 64 + c]);
                const uint32_t h1 = pack_f16x2(Wbg2[(kb + 2) * 64 + c], Wbg2[(kb + 3) * 64 + c]);
                *(uint2*)(g_Wimg + 9216 + off) = make_uint2(h0, h1);
            }
        }
        return;
    }

    extern __shared__ char smp[];
    const uint32_t sb = smem_to_u32(smp);

    // --- vectorized W conversion: thread owns (c, k-quad) ---
    #define CVT4_HL(SRC, OFF) {                                              \
        uint32_t h0_, l0_, h1_, l1_;                                         \
        dpack((SRC)[(kb + 0) * 64 + c], (SRC)[(kb + 1) * 64 + c], h0_, l0_); \
        dpack((SRC)[(kb + 2) * 64 + c], (SRC)[(kb + 3) * 64 + c], h1_, l1_); \
        *(uint2*)(smp + (OFF) + off)        = make_uint2(h0_, h1_);          \
        *(uint2*)(smp + (OFF) + 9216 + off) = make_uint2(l0_, l1_); }
    #define CVT4_H(SRC, BASEOFF, OFF) {                                      \
        const uint32_t h0_ = pack_f16x2((SRC)[(BASEOFF) + (kb + 0) * 64 + c],\
                                        (SRC)[(BASEOFF) + (kb + 1) * 64 + c]);\
        const uint32_t h1_ = pack_f16x2((SRC)[(BASEOFF) + (kb + 2) * 64 + c],\
                                        (SRC)[(BASEOFF) + (kb + 3) * 64 + c]);\
        *(uint2*)(smp + (OFF) + off) = make_uint2(h0_, h1_); }
    for (int tq = tid; tq < 1024; tq += 128) {
        const int c  = tq & 63;
        const int kb = (tq >> 6) * 4;
        const int off = c * PP + kb * 2;
        CVT4_HL(Wlin, P_WLIN)
        CVT4_HL(Wu1,  P_WU1)
        CVT4_HL(Wu2,  P_WU2)
        CVT4_HL(Wug1, P_WUG1)
        CVT4_HL(Wug2, P_WUG2)
        CVT4_H(Wb1,  0,    P_WB1A)
        CVT4_H(Wb1,  4096, P_WB1B)
        CVT4_H(Wbg1, 0,    P_WBG1A)
        CVT4_H(Wbg1, 4096, P_WBG1B)
    }
    #undef CVT4_HL
    #undef CVT4_H

    // --- stage x rows (64 per block) as hi/lo fp16 A tiles ---
    {
        const int row  = tid >> 1;           // 0..63
        const int part = tid & 1;            // k-half
        const int swz  = ((row >> 3) & 1) * 4;
        const int row_g = blockIdx.x * 64 + row;
        #pragma unroll
        for (int qi = 0; qi < 4; qi++) {
            const int q  = part * 4 + qi;
            const int k0 = q * 8;
            const float4 v0 = *(const float4*)(x + row_g * 64 + k0);
            const float4 v1 = *(const float4*)(x + row_g * 64 + k0 + 4);
            uint32_t h0, l0, h1, l1, h2, l2, h3, l3;
            dpack(v0.x, v0.y, h0, l0);
            dpack(v0.z, v0.w, h1, l1);
            dpack(v1.x, v1.y, h2, l2);
            dpack(v1.z, v1.w, h3, l3);
            const int boff = row * PP + ((q ^ swz) * 16);
            *(uint4*)(smp + P_XH + boff) = make_uint4(h0, h1, h2, h3);
            *(uint4*)(smp + P_XL + boff) = make_uint4(l0, l1, l2, l3);
        }
    }
    __syncthreads();

    // --- per-warp chain ---
    const int w    = tid >> 5;
    const int lane = tid & 31;
    const int gid  = lane >> 2;
    const int tig  = lane & 3;
    const int arow0 = w * 16 + (lane & 15);
    const int lsw   = ((lane >> 3) & 1) * 4;
    const int lch   = lane >> 4;
    const int row_g0 = blockIdx.x * 64 + w * 16;

    #define PGEMM3(ACC, AH, AL, WOFF)                                        \
        _Pragma("unroll")                                                    \
        for (int ks = 0; ks < 4; ks++) {                                     \
            _Pragma("unroll")                                                \
            for (int nt = 0; nt < 8; nt++) {                                 \
                const char* wp_ = smp + (WOFF) +                             \
                    (nt * 8 + gid) * PP + ks * 32 + 4 * tig;                 \
                const uint32_t wh0 = *(const uint32_t*)(wp_);                \
                const uint32_t wh1 = *(const uint32_t*)(wp_ + 16);           \
                const uint32_t wl0 = *(const uint32_t*)(wp_ + 9216);         \
                const uint32_t wl1 = *(const uint32_t*)(wp_ + 9216 + 16);    \
                mma16816(ACC[nt], AH[ks], wh0, wh1);                         \
                mma16816(ACC[nt], AL[ks], wh0, wh1);                         \
                mma16816(ACC[nt], AH[ks], wl0, wl1);                         \
            }                                                                \
        }
    // paired single-pass GEMMs: two independent accumulator sets, shared
    // index arithmetic -> 2x MMA ILP with only 4 warps/SM
    #define PGEMM1_DUAL(ACC1, ACC2, AH, WOFF1, WOFF2)                        \
        _Pragma("unroll")                                                    \
        for (int ks = 0; ks < 4; ks++) {                                     \
            _Pragma("unroll")                                                \
            for (int nt = 0; nt < 8; nt++) {                                 \
                const int wo_ = (nt * 8 + gid) * PP + ks * 32 + 4 * tig;     \
                const char* wp1_ = smp + (WOFF1) + wo_;                      \
                const char* wp2_ = smp + (WOFF2) + wo_;                      \
                const uint32_t a0_ = *(const uint32_t*)(wp1_);               \
                const uint32_t a1_ = *(const uint32_t*)(wp1_ + 16);          \
                const uint32_t b0_ = *(const uint32_t*)(wp2_);               \
                const uint32_t b1_ = *(const uint32_t*)(wp2_ + 16);          \
                mma16816(ACC1[nt], AH[ks], a0_, a1_);                        \
                mma16816(ACC2[nt], AH[ks], b0_, b1_);                        \
            }                                                                \
        }
    #define ZACC(ACC)                                                        \
        _Pragma("unroll")                                                    \
        for (int nt = 0; nt < 8; nt++)                                       \
            _Pragma("unroll")                                                \
            for (int r = 0; r < 4; r++) ACC[nt][r] = 0.f;
    #define ADD_BIAS(ACC, BP)                                                \
        _Pragma("unroll")                                                    \
        for (int nt = 0; nt < 8; nt++) {                                     \
            const float2 bv = *(const float2*)((BP) + nt * 8 + 2 * tig);     \
            ACC[nt][0] += bv.x; ACC[nt][1] += bv.y;                          \
            ACC[nt][2] += bv.x; ACC[nt][3] += bv.y;                          \
        }
    #define DPACK_FRAGS(AH, AL, ACC)                                         \
        _Pragma("unroll")                                                    \
        for (int ks = 0; ks < 4; ks++) {                                     \
            dpack(ACC[2*ks][0],   ACC[2*ks][1],   AH[ks][0], AL[ks][0]);     \
            dpack(ACC[2*ks][2],   ACC[2*ks][3],   AH[ks][1], AL[ks][1]);     \
            dpack(ACC[2*ks+1][0], ACC[2*ks+1][1], AH[ks][2], AL[ks][2]);     \
            dpack(ACC[2*ks+1][2], ACC[2*ks+1][3], AH[ks][3], AL[ks][3]);     \
        }
    #define TANH_ACC(ACC)                                                    \
        _Pragma("unroll")                                                    \
        for (int nt = 0; nt < 8; nt++)                                       \
            _Pragma("unroll")                                                \
            for (int r = 0; r < 4; r++) ACC[nt][r] = tanh_fast(ACC[nt][r]);
    #define STORE_ACC(ACC, GP)                                               \
        _Pragma("unroll")                                                    \
        for (int nt = 0; nt < 8; nt++) {                                     \
            const int c_ = nt * 8 + 2 * tig;                                 \
            *(float2*)((GP) + (row_g0 + gid) * 64 + c_) =                    \
                make_float2(ACC[nt][0], ACC[nt][1]);                         \
            *(float2*)((GP) + (row_g0 + gid + 8) * 64 + c_) =                \
                make_float2(ACC[nt][2], ACC[nt][3]);                         \
        }

    uint32_t axh[4][4], axl[4][4];
    #pragma unroll
    for (int ks = 0; ks < 4; ks++) {
        const uint32_t ad = sb + P_XH + (uint32_t)(arow0 * PP)
                          + (uint32_t)((((ks * 2 + lch) ^ lsw)) * 16);
        ldm_x4(axh[ks], ad);
        ldm_x4(axl[ks], ad + 9216);
    }

    float acc[8][4];

    // h = x @ Wlin + blin
    ZACC(acc)
    PGEMM3(acc, axh, axl, P_WLIN)
    ADD_BIAS(acc, blin)
    uint32_t ahh[4][4], ahl[4][4];
    DPACK_FRAGS(ahh, ahl, acc)

    // t1 = tanh(h @ Wu1 + bu1)
    ZACC(acc)
    PGEMM3(acc, ahh, ahl, P_WU1)
    ADD_BIAS(acc, bu1)
    TANH_ACC(acc)
    uint32_t ath[4][4], atl[4][4];
    DPACK_FRAGS(ath, atl, acc)

    // um = t1 @ Wu2 + bu2
    float um[8][4];
    #pragma unroll
    for (int nt = 0; nt < 8; nt++)
        #pragma unroll
        for (int r = 0; r < 4; r++) um[nt][r] = 0.f;
    PGEMM3(um, ath, atl, P_WU2)
    ADD_BIAS(um, bu2)

    // t2 = tanh(h @ Wug1 + bug1)
    ZACC(acc)
    PGEMM3(acc, ahh, ahl, P_WUG1)
    ADD_BIAS(acc, bug1)
    TANH_ACC(acc)
    DPACK_FRAGS(ath, atl, acc)

    // ug = sigmoid(t2 @ Wug2 + bug2); U = um * ug
    ZACC(acc)
    PGEMM3(acc, ath, atl, P_WUG2)
    ADD_BIAS(acc, bug2)
    #pragma unroll
    for (int nt = 0; nt < 8; nt++)
        #pragma unroll
        for (int r = 0; r < 4; r++)
            acc[nt][r] = um[nt][r] * fast_sigmoid(acc[nt][r]);
    STORE_ACC(acc, g_U)

    // binary factors: paired single-pass GEMMs (2x ILP)
    float acc2[8][4];
    ZACC(acc)
    ZACC(acc2)
    PGEMM1_DUAL(acc, acc2, ahh, P_WB1A, P_WB1B)
    ADD_BIAS(acc, bb1)
    STORE_ACC(acc, g_A)
    STORE_ACC(acc2, g_B)

    ZACC(acc)
    ZACC(acc2)
    PGEMM1_DUAL(acc, acc2, ahh, P_WBG1A, P_WBG1B)
    ADD_BIAS(acc, bbg1)
    STORE_ACC(acc, g_Ag)
    STORE_ACC(acc2, g_Bg)
}

// ---------------------------------------------------------------------------
// Kernel 2 (R16 structure + STS.128 build remap): one block per (n, 4 j's).
// 2048 blocks x 256 threads. Fused prologue (one sync), 2 back-to-back
// MMA+epilogue passes; finalize(t0) overlaps MMA(t1).
// Build thread mapping: (row-quad r4 = tid>>3, 8-float chunk ch8 = tid&7):
// B loads coalesced per quarter-warp; ONE STS.128 per (pass,jj) -> half the
// store instructions, identical smem layout.
// ---------------------------------------------------------------------------
#define WPITCH_B  144
#define OFF_WB    0
#define OFF_WG    9216
#define OFF_A     18432
#define OFF_BB2   92160
#define OFF_BBG2  92416
#define OFF_PART0 92672
#define OFF_PART1 93696
#define MAIN_SMEM_BYTES 94720

__global__ __launch_bounds__(256, 2)
void main_kernel(const float* __restrict__ bb2, const float* __restrict__ bbg2,
                 float* __restrict__ out)
{
    extern __shared__ char smem[];
    const uint32_t sb = smem_to_u32(smem);
    const int tid  = threadIdx.x;
    const int wid  = tid >> 5;
    const int lane = tid & 31;
    const int gid  = lane >> 2;
    const int tig  = lane & 3;
    const int n    = blockIdx.x >> 4;
    const int jg   = blockIdx.x & 15;
    const int j0   = jg * 4;

    // ---- fused prologue (no sync until everything staged) ----
    {
        const uint4* wsrc = (const uint4*)g_Wimg;
        uint4* wdst = (uint4*)smem;
        for (int idx = tid; idx < 1152; idx += 256)
            wdst[idx] = wsrc[idx];
    }
    float* sbb2  = (float*)(smem + OFF_BB2);
    float* sbbg2 = (float*)(smem + OFF_BBG2);
    if (tid < 64) { sbb2[tid] = bb2[tid]; sbbg2[tid] = bbg2[tid]; }
    float uPre0 = 0.f, uPre1 = 0.f;
    int oIdx0 = 0, oIdx1 = 0;
    if (tid < 128) {
        const int jj = tid >> 6;
        const int c  = tid & 63;
        oIdx0 = (n * 64 + j0 + 0 + jj) * 64 + c;
        oIdx1 = (n * 64 + j0 + 2 + jj) * 64 + c;
        uPre0 = g_U[oIdx0];
        uPre1 = g_U[oIdx1];
    }
    // fused build: all 4 A tiles; (r4, ch8) mapping with STS.128 stores
    {
        const int r4  = tid >> 3;            // 0..31 (i-row within pass)
        const int ch8 = tid & 7;             // 8-float (16B-fp16) chunk
        #pragma unroll
        for (int p = 0; p < 2; p++) {
            const float* Bsrc = (p ? g_Bg : g_B) + n * 4096;
            const float* Asrc = (p ? g_Ag : g_A) + (n * 64 + j0) * 64 + 8 * ch8;
            float4 aq[4][2];
            #pragma unroll
            for (int jj = 0; jj < 4; jj++) {
                aq[jj][0] = *(const float4*)(Asrc + jj * 64);
                aq[jj][1] = *(const float4*)(Asrc + jj * 64 + 4);
            }
            #pragma unroll
            for (int pass = 0; pass < 2; pass++) {
                const int i = pass * 32 + r4;
                const float4 b0 = *(const float4*)(Bsrc + i * 64 + 8 * ch8);
                const float4 b1 = *(const float4*)(Bsrc + i * 64 + 8 * ch8 + 4);
                const int swz  = ((i >> 3) & 1) * 4;
                const int coff = ((ch8 ^ swz) * 16);
                #pragma unroll
                for (int jj = 0; jj < 4; jj++) {
                    const int tile = jj >> 1;
                    const int row  = (jj & 1) * 64 + i;
                    char* dst = smem + OFF_A + (tile * 2 + p) * 18432;
                    const uint32_t h0 = tanh_f16x2(pack_f16x2(aq[jj][0].x + b0.x, aq[jj][0].y + b0.y));
                    const uint32_t h1 = tanh_f16x2(pack_f16x2(aq[jj][0].z + b0.z, aq[jj][0].w + b0.w));
                    const uint32_t h2 = tanh_f16x2(pack_f16x2(aq[jj][1].x + b1.x, aq[jj][1].y + b1.y));
                    const uint32_t h3 = tanh_f16x2(pack_f16x2(aq[jj][1].z + b1.z, aq[jj][1].w + b1.w));
                    *(uint4*)(dst + row * WPITCH_B + coff) = make_uint4(h0, h1, h2, h3);
                }
            }
        }
    }
    __syncthreads();   // single prologue sync

    // MMA mapping: 32m x 32n warp tiles
    const int ms    = wid & 3;
    const int nh    = wid >> 2;
    const int m0    = 32 * ms;
    const int cb    = 32 * nh;
    const int arow0 = m0 + (lane & 15);
    const int lsw   = ((lane >> 3) & 1) * 4;
    const int lch   = lane >> 4;

    #pragma unroll
    for (int tt = 0; tt < 2; tt++) {
        const uint32_t Abase = sb + OFF_A + (uint32_t)(tt * 36864);

        float accb[2][4][4], accg[2][4][4];
        #pragma unroll
        for (int s = 0; s < 2; s++)
            #pragma unroll
            for (int nt = 0; nt < 4; nt++)
                #pragma unroll
                for (int r = 0; r < 4; r++) { accb[s][nt][r] = 0.f; accg[s][nt][r] = 0.f; }

        #pragma unroll
        for (int ks = 0; ks < 4; ks++) {
            const uint32_t chunk = (uint32_t)(((ks * 2 + lch) ^ lsw) * 16);
            uint32_t ah0[4], ah1[4];
            {
                const uint32_t ad0 = Abase + (uint32_t)(arow0 * WPITCH_B) + chunk;
                ldm_x4(ah0, ad0);
                ldm_x4(ah1, ad0 + 16 * WPITCH_B);
                #pragma unroll
                for (int nt = 0; nt < 4; nt++) {
                    const char* wp = (const char*)smem + OFF_WB +
                        (cb + nt * 8 + gid) * WPITCH_B + ks * 32 + 4 * tig;
                    const uint32_t h0 = *(const uint32_t*)(wp);
                    const uint32_t h1 = *(const uint32_t*)(wp + 16);
                    mma16816(accb[0][nt], ah0, h0, h1);
                    mma16816(accb[1][nt], ah1, h0, h1);
                }
            }
            {
                const uint32_t ad0 = Abase + 18432u + (uint32_t)(arow0 * WPITCH_B) + chunk;
                ldm_x4(ah0, ad0);
                ldm_x4(ah1, ad0 + 16 * WPITCH_B);
                #pragma unroll
                for (int nt = 0; nt < 4; nt++) {
                    const char* wp = (const char*)smem + OFF_WG +
                        (cb + nt * 8 + gid) * WPITCH_B + ks * 32 + 4 * tig;
                    const uint32_t h0 = *(const uint32_t*)(wp);
                    const uint32_t h1 = *(const uint32_t*)(wp + 16);
                    mma16816(accg[0][nt], ah0, h0, h1);
                    mma16816(accg[1][nt], ah1, h0, h1);
                }
            }
        }

        float* partS = (float*)(smem + (tt ? OFF_PART1 : OFF_PART0));
        #pragma unroll
        for (int nt = 0; nt < 4; nt++) {
            const int c0 = cb + nt * 8 + 2 * tig;
            const float2 bb = *(const float2*)(sbb2 + c0);
            const float2 gb = *(const float2*)(sbbg2 + c0);
            float p0 = 0.f, p1 = 0.f;
            #pragma unroll
            for (int s = 0; s < 2; s++) {
                const float g0 = accg[s][nt][0] + gb.x;
                const float g1 = accg[s][nt][1] + gb.y;
                const float g2 = accg[s][nt][2] + gb.x;
                const float g3 = accg[s][nt][3] + gb.y;
                uint32_t ta = tanh_f16x2(pack_f16x2(0.5f * g0, 0.5f * g1));
                uint32_t tb = tanh_f16x2(pack_f16x2(0.5f * g2, 0.5f * g3));
                const float2 fa = __half22float2(*(__half2*)&ta);
                const float2 fb = __half22float2(*(__half2*)&tb);
                p0 += (accb[s][nt][0] + bb.x) * fmaf(fa.x, 0.5f, 0.5f)
                    + (accb[s][nt][2] + bb.x) * fmaf(fb.x, 0.5f, 0.5f);
                p1 += (accb[s][nt][1] + bb.y) * fmaf(fa.y, 0.5f, 0.5f)
                    + (accb[s][nt][3] + bb.y) * fmaf(fb.y, 0.5f, 0.5f);
            }
            p0 += __shfl_xor_sync(0xFFFFFFFFu, p0, 4);
            p1 += __shfl_xor_sync(0xFFFFFFFFu, p1, 4);
            p0 += __shfl_xor_sync(0xFFFFFFFFu, p0, 8);
            p1 += __shfl_xor_sync(0xFFFFFFFFu, p1, 8);
            p0 += __shfl_xor_sync(0xFFFFFFFFu, p0, 16);
            p1 += __shfl_xor_sync(0xFFFFFFFFu, p1, 16);
            if (lane < 4)
                *(float2*)(partS + wid * 32 + nt * 8 + 2 * lane) = make_float2(p0, p1);
        }
        __syncthreads();

        if (tid < 128) {
            const int jj = tid >> 6;
            const int c  = tid & 63;
            const int w1 = (c >> 5) * 4 + 2 * jj;
            const int cl = c & 31;
            const float sum = partS[w1 * 32 + cl] + partS[(w1 + 1) * 32 + cl];
            if (tt == 0) out[oIdx0] = uPre0 + sum * (1.0f / 63.0f);
            else         out[oIdx1] = uPre1 + sum * (1.0f / 63.0f);
        }
    }
}

// ---------------------------------------------------------------------------
// launch
// ---------------------------------------------------------------------------
extern "C" void kernel_launch(void* const* d_in, const int* in_sizes, int n_in,
                              void* d_out, int out_size)
{
    const float* x    = (const float*)d_in[0];
    const float* Wlin = (const float*)d_in[1];
    const float* blin = (const float*)d_in[2];
    const float* Wu1  = (const float*)d_in[3];
    const float* bu1  = (const float*)d_in[4];
    const float* Wu2  = (const float*)d_in[5];
    const float* bu2  = (const float*)d_in[6];
    const float* Wug1 = (const float*)d_in[7];
    const float* bug1 = (const float*)d_in[8];
    const float* Wug2 = (const float*)d_in[9];
    const float* bug2 = (const float*)d_in[10];
    const float* Wb1  = (const float*)d_in[11];
    const float* bb1  = (const float*)d_in[12];
    const float* Wb2  = (const float*)d_in[13];
    const float* bb2  = (const float*)d_in[14];
    const float* Wbg1 = (const float*)d_in[15];
    const float* bbg1 = (const float*)d_in[16];
    const float* Wbg2 = (const float*)d_in[17];
    const float* bbg2 = (const float*)d_in[18];

    float* out = (float*)d_out;

    cudaFuncSetAttribute(prep_kernel, cudaFuncAttributeMaxDynamicSharedMemorySize, PREP_SMEM_BYTES);
    cudaFuncSetAttribute(main_kernel, cudaFuncAttributeMaxDynamicSharedMemorySize, MAIN_SMEM_BYTES);

    prep_kernel<<<129, 128, PREP_SMEM_BYTES>>>(x, Wlin, blin, Wu1, bu1, Wu2, bu2,
                                               Wug1, bug1, Wug2, bug2,
                                               Wb1, bb1, Wbg1, bbg1, Wb2, Wbg2);
    main_kernel<<<2048, 256, MAIN_SMEM_BYTES>>>(bb2, bbg2, out);
}